// round 7
// baseline (speedup 1.0000x reference)
#include <cuda_runtime.h>
#include <math.h>
#include <stdint.h>

#define NB 32
#define NT 36
#define NN 10000
#define NF 3
#define NH 10
#define NR 20
#define PRED_ELEMS (NB * NH * NN)   // 3,200,000
#define NODES_PER_BLK 256
#define NBLK_X ((NN + NODES_PER_BLK - 1) / NODES_PER_BLK)   // 40
#define NBLOCKS (NBLK_X * NB)                               // 1280
#define ROW_BYTES (NN * NF * 4)                             // 120000 B per (b,t) row
#define TILE_BYTES (NODES_PER_BLK * NF * 4)                 // 3072 B per stage
#define NSTAGE 4

// ---------------- device scratch (zero-initialized at module load; ----------------
// ---------------- last block restores zeros every launch -> replay-safe) ----------
__device__ float g_rsum[NB * NR];
__device__ float g_rcnt[NB * NR];
__device__ int   g_nan_count;
__device__ int   g_nan_list[NB * NN];
__device__ unsigned int g_done;

__device__ __forceinline__ uint32_t smem_u32(const void* p) {
    uint32_t a;
    asm("{ .reg .u64 t; cvta.to.shared.u64 t, %1; cvt.u32.u64 %0, t; }"
        : "=r"(a) : "l"(p));
    return a;
}

__device__ __forceinline__ void mbar_init(uint32_t bar, uint32_t cnt) {
    asm volatile("mbarrier.init.shared.b64 [%0], %1;" :: "r"(bar), "r"(cnt) : "memory");
}
__device__ __forceinline__ void mbar_expect_tx(uint32_t bar, uint32_t bytes) {
    asm volatile("mbarrier.arrive.expect_tx.shared.b64 _, [%0], %1;"
                 :: "r"(bar), "r"(bytes) : "memory");
}
__device__ __forceinline__ void bulk_ld(uint32_t dst, const void* src,
                                        uint32_t bytes, uint32_t bar) {
    asm volatile(
        "cp.async.bulk.shared::cluster.global.mbarrier::complete_tx::bytes "
        "[%0], [%1], %2, [%3];"
        :: "r"(dst), "l"(src), "r"(bytes), "r"(bar) : "memory");
}
__device__ __forceinline__ void mbar_wait(uint32_t bar, uint32_t parity) {
    asm volatile(
        "{\n\t"
        ".reg .pred P;\n\t"
        "WAIT_%=:\n\t"
        "mbarrier.try_wait.parity.acquire.cta.shared::cta.b64 P, [%0], %1, 0x989680;\n\t"
        "@P bra.uni DONE_%=;\n\t"
        "bra.uni WAIT_%=;\n\t"
        "DONE_%=:\n\t"
        "}"
        :: "r"(bar), "r"(parity) : "memory");
}

// ---------------- K1: TMA-pipelined time-mean + region accum + broadcast ----------------
// grid (40, 32), block 256; block covers 256 nodes of one batch.
__global__ void __launch_bounds__(256) k1_fused(
    const float* __restrict__ seq, const int* __restrict__ cid32,
    float* __restrict__ out) {
    const int b = blockIdx.y;
    const int n0 = blockIdx.x * NODES_PER_BLK;
    const int tid = threadIdx.x;
    const int n = n0 + tid;

    __shared__ __align__(128) char s_tile[NSTAGE][TILE_BYTES];
    __shared__ __align__(8) uint64_t s_bar[NSTAGE];
    __shared__ float s_rsum[NR];
    __shared__ float s_rcnt[NR];

    if (tid < NR) { s_rsum[tid] = 0.0f; s_rcnt[tid] = 0.0f; }
    if (tid == 0) {
#pragma unroll
        for (int s = 0; s < NSTAGE; s++) mbar_init(smem_u32(&s_bar[s]), 1);
    }

    // int64-vs-int32 probe for cluster_id (if int64, all odd words are 0).
    int bad = 0;
    if (tid < 64) bad = (cid32[2 * tid + 1] != 0);
    const int is64 = (__syncthreads_or(bad) == 0);  // also orders mbar_init / smem init

    const uint32_t tile_bytes =
        (uint32_t)((n0 + NODES_PER_BLK <= NN ? NODES_PER_BLK : NN - n0) * NF * 4);
    const char* gsrc = (const char*)seq + (size_t)b * NT * ROW_BYTES + (size_t)n0 * NF * 4;

    // prologue: fill stages 0..NSTAGE-1
    if (tid == 0) {
#pragma unroll
        for (int t = 0; t < NSTAGE; t++) {
            uint32_t bar = smem_u32(&s_bar[t]);
            mbar_expect_tx(bar, tile_bytes);
            bulk_ld(smem_u32(&s_tile[t][0]), gsrc + (size_t)t * ROW_BYTES,
                    tile_bytes, bar);
        }
    }

    float sum = 0.0f, cnt = 0.0f;
#pragma unroll
    for (int t = 0; t < NT; t++) {
        const int slot = t % NSTAGE;
        const uint32_t parity = (t / NSTAGE) & 1;
        mbar_wait(smem_u32(&s_bar[slot]), parity);
        float x = *(const float*)&s_tile[slot][tid * (NF * 4)];  // channel 0
        if (x == x) { sum += x; cnt += 1.0f; }
        __syncthreads();   // all reads of this slot done before refill
        if (tid == 0 && t + NSTAGE < NT) {
            uint32_t bar = smem_u32(&s_bar[slot]);
            mbar_expect_tx(bar, tile_bytes);
            bulk_ld(smem_u32(&s_tile[slot][0]),
                    gsrc + (size_t)(t + NSTAGE) * ROW_BYTES, tile_bytes, bar);
        }
    }

    if (n < NN) {
        const float tm = sum / cnt;          // 0/0 -> NaN when node all-NaN
#pragma unroll
        for (int h = 0; h < NH; h++) {
            out[(size_t)(b * NH + h) * NN + n] = tm;
        }
        if (tm == tm) {
            const int r = is64 ? cid32[2 * n] : cid32[n];
            atomicAdd(&s_rsum[r], tm);
            atomicAdd(&s_rcnt[r], 1.0f);
        } else {
            int idx = atomicAdd(&g_nan_count, 1);
            g_nan_list[idx] = b * NN + n;
        }
    }
    __syncthreads();
    if (tid < NR) {
        atomicAdd(&g_rsum[b * NR + tid], s_rsum[tid]);
    } else if (tid < 2 * NR) {
        const int r = tid - NR;
        atomicAdd(&g_rcnt[b * NR + r], s_rcnt[r]);
    }

    // ---------------- last-block finalization ----------------
    __threadfence();
    __shared__ unsigned int s_ticket;
    __syncthreads();
    if (tid == 0) s_ticket = atomicAdd(&g_done, 1u);
    __syncthreads();
    if (s_ticket != NBLOCKS - 1) return;

    float v0 = 0.f, v1 = 0.f, v2 = 0.f, v3 = 0.f;
    for (int i = tid; i < NB * NR; i += 256) {
        const float rs = g_rsum[i];
        const float rc = g_rcnt[i];
        const float reg = rs / rc;
        v0 += rs; v1 += rc;
        if (reg == reg) { v2 += reg; v3 += 1.0f; }
    }
#pragma unroll
    for (int o = 16; o > 0; o >>= 1) {
        v0 += __shfl_down_sync(0xFFFFFFFFu, v0, o);
        v1 += __shfl_down_sync(0xFFFFFFFFu, v1, o);
        v2 += __shfl_down_sync(0xFFFFFFFFu, v2, o);
        v3 += __shfl_down_sync(0xFFFFFFFFu, v3, o);
    }
    __shared__ float sw[8][4];
    const int w = tid >> 5, l = tid & 31;
    if (l == 0) { sw[w][0] = v0; sw[w][1] = v1; sw[w][2] = v2; sw[w][3] = v3; }
    __syncthreads();
    __shared__ float s_g1, s_g2;
    if (w == 0) {
        float a0 = (l < 8) ? sw[l][0] : 0.0f;
        float a1 = (l < 8) ? sw[l][1] : 0.0f;
        float a2 = (l < 8) ? sw[l][2] : 0.0f;
        float a3 = (l < 8) ? sw[l][3] : 0.0f;
#pragma unroll
        for (int o = 4; o > 0; o >>= 1) {
            a0 += __shfl_down_sync(0xFFFFFFFFu, a0, o);
            a1 += __shfl_down_sync(0xFFFFFFFFu, a1, o);
            a2 += __shfl_down_sync(0xFFFFFFFFu, a2, o);
            a3 += __shfl_down_sync(0xFFFFFFFFu, a3, o);
        }
        if (l == 0) { s_g1 = a0 / a1; s_g2 = a2 / a3; }
    }
    __syncthreads();
    const float g1 = s_g1, g2 = s_g2;

    float* outR = out + PRED_ELEMS;
    for (int i = tid; i < NB * NR; i += 256) {
        const int bb = i / NR, rr = i % NR;
        const float reg = g_rsum[i] / g_rcnt[i];
        const float val = (reg == reg) ? reg : g2;
#pragma unroll
        for (int h = 0; h < NH; h++) {
            outR[(bb * NH + h) * NR + rr] = val;
        }
        g_rsum[i] = 0.0f;
        g_rcnt[i] = 0.0f;
    }

    const int cc = g_nan_count;
    for (int idx = tid; idx < cc; idx += 256) {
        const int bn = g_nan_list[idx];
        const int bb = bn / NN, nn = bn % NN;
#pragma unroll
        for (int h = 0; h < NH; h++) {
            out[(size_t)(bb * NH + h) * NN + nn] = g1;
        }
    }
    if (tid == 0) {
        g_nan_count = 0;
        g_done = 0;
    }
}

// ---------------- launcher ----------------
extern "C" void kernel_launch(void* const* d_in, const int* in_sizes, int n_in,
                              void* d_out, int out_size) {
    const float* seq = (const float*)d_in[0];
    const int* cid = (const int*)d_in[1];
    float* out = (float*)d_out;

    dim3 grid(NBLK_X, NB);
    k1_fused<<<grid, 256>>>(seq, cid, out);
}

// round 9
// speedup vs baseline: 1.2115x; 1.2115x over previous
#include <cuda_runtime.h>
#include <math.h>

#define NB 32
#define NT 36
#define NN 10000
#define NF 3
#define NH 10
#define NR 20
#define PRED_ELEMS (NB * NH * NN)   // 3,200,000
#define NBLK_X ((NN + 255) / 256)   // 40
#define NBLOCKS (NBLK_X * NB)       // 1280
#define TBATCH 12                   // loads kept in flight per batch

// ---------------- device scratch (zero-initialized at module load; ----------------
// ---------------- last block restores zeros every launch -> replay-safe) ----------
__device__ float g_rsum[NB * NR];
__device__ float g_rcnt[NB * NR];
__device__ int   g_nan_count;
__device__ int   g_nan_list[NB * NN];
__device__ unsigned int g_done;

// ---------------- K1: everything in one kernel ----------------
// grid (40, 32), block 256; one thread per (b, n).
// Scalar stride-12B loads (warp covers 384 contiguous B per t -> optimal L1
// wavefronts). __launch_bounds__(256, 4) lifts the reg cap to ~64 so ptxas can
// keep a 12-deep load batch in flight per thread (R6's 32-reg/8-block config
// starved MLP at DRAM=57%).
__global__ void __launch_bounds__(256, 4) k1_fused(
    const float* __restrict__ seq, const int* __restrict__ cid32,
    float* __restrict__ out) {
    const int b = blockIdx.y;
    const int n = blockIdx.x * blockDim.x + threadIdx.x;
    const int tid = threadIdx.x;

    __shared__ float s_rsum[NR];
    __shared__ float s_rcnt[NR];
    if (tid < NR) { s_rsum[tid] = 0.0f; s_rcnt[tid] = 0.0f; }

    // int64-vs-int32 probe for cluster_id (if int64, all odd words are 0;
    // values 0..19 -> misfire P = 20^-64).
    int bad = 0;
    if (tid < 64) bad = (cid32[2 * tid + 1] != 0);
    const int is64 = (__syncthreads_or(bad) == 0);   // also covers smem init sync

    if (n < NN) {
        const float* base = seq + (size_t)b * (NT * NN * NF) + (size_t)n * NF;
        float s = 0.0f, c = 0.0f;
#pragma unroll
        for (int tb = 0; tb < NT / TBATCH; tb++) {
            float x[TBATCH];
#pragma unroll
            for (int k = 0; k < TBATCH; k++) {
                x[k] = __ldg(base + (size_t)(tb * TBATCH + k) * (NN * NF));
            }
#pragma unroll
            for (int k = 0; k < TBATCH; k++) {
                if (x[k] == x[k]) { s += x[k]; c += 1.0f; }
            }
        }
        const float tm = s / c;             // 0/0 -> NaN when node all-NaN

        // broadcast the 10 horizon copies (store pipe idle under load latency)
#pragma unroll
        for (int h = 0; h < NH; h++) {
            out[(size_t)(b * NH + h) * NN + n] = tm;
        }

        if (tm == tm) {
            const int r = is64 ? cid32[2 * n] : cid32[n];
            atomicAdd(&s_rsum[r], tm);
            atomicAdd(&s_rcnt[r], 1.0f);
        } else {
            int idx = atomicAdd(&g_nan_count, 1);
            g_nan_list[idx] = b * NN + n;
        }
    }
    __syncthreads();
    if (tid < NR) {
        atomicAdd(&g_rsum[b * NR + tid], s_rsum[tid]);
    } else if (tid < 2 * NR) {
        const int r = tid - NR;
        atomicAdd(&g_rcnt[b * NR + r], s_rcnt[r]);
    }

    // ---------------- last-block finalization ----------------
    __threadfence();
    __shared__ unsigned int s_ticket;
    __syncthreads();
    if (tid == 0) s_ticket = atomicAdd(&g_done, 1u);
    __syncthreads();
    if (s_ticket != NBLOCKS - 1) return;

    // v0/v1 -> g1 (valid-node sum/count); v2/v3 -> g2 (mean of valid regional)
    float v0 = 0.f, v1 = 0.f, v2 = 0.f, v3 = 0.f;
    for (int i = tid; i < NB * NR; i += 256) {
        const float rs = g_rsum[i];
        const float rc = g_rcnt[i];
        const float reg = rs / rc;
        v0 += rs; v1 += rc;
        if (reg == reg) { v2 += reg; v3 += 1.0f; }
    }
#pragma unroll
    for (int o = 16; o > 0; o >>= 1) {
        v0 += __shfl_down_sync(0xFFFFFFFFu, v0, o);
        v1 += __shfl_down_sync(0xFFFFFFFFu, v1, o);
        v2 += __shfl_down_sync(0xFFFFFFFFu, v2, o);
        v3 += __shfl_down_sync(0xFFFFFFFFu, v3, o);
    }
    __shared__ float sw[8][4];
    const int w = tid >> 5, l = tid & 31;
    if (l == 0) { sw[w][0] = v0; sw[w][1] = v1; sw[w][2] = v2; sw[w][3] = v3; }
    __syncthreads();
    __shared__ float s_g1, s_g2;
    if (w == 0) {
        float a0 = (l < 8) ? sw[l][0] : 0.0f;
        float a1 = (l < 8) ? sw[l][1] : 0.0f;
        float a2 = (l < 8) ? sw[l][2] : 0.0f;
        float a3 = (l < 8) ? sw[l][3] : 0.0f;
#pragma unroll
        for (int o = 4; o > 0; o >>= 1) {
            a0 += __shfl_down_sync(0xFFFFFFFFu, a0, o);
            a1 += __shfl_down_sync(0xFFFFFFFFu, a1, o);
            a2 += __shfl_down_sync(0xFFFFFFFFu, a2, o);
            a3 += __shfl_down_sync(0xFFFFFFFFu, a3, o);
        }
        if (l == 0) { s_g1 = a0 / a1; s_g2 = a2 / a3; }
    }
    __syncthreads();
    const float g1 = s_g1, g2 = s_g2;

    // regional output (NaN regions -> g2), then re-zero accumulators
    float* outR = out + PRED_ELEMS;
    for (int i = tid; i < NB * NR; i += 256) {
        const int bb = i / NR, rr = i % NR;
        const float reg = g_rsum[i] / g_rcnt[i];
        const float val = (reg == reg) ? reg : g2;
#pragma unroll
        for (int h = 0; h < NH; h++) {
            outR[(bb * NH + h) * NR + rr] = val;
        }
        g_rsum[i] = 0.0f;
        g_rcnt[i] = 0.0f;
    }

    // fix the (statistically nonexistent) all-NaN pred cells with g1
    const int cnt = g_nan_count;
    for (int idx = tid; idx < cnt; idx += 256) {
        const int bn = g_nan_list[idx];
        const int bb = bn / NN, nn = bn % NN;
#pragma unroll
        for (int h = 0; h < NH; h++) {
            out[(size_t)(bb * NH + h) * NN + nn] = g1;
        }
    }
    if (tid == 0) {
        g_nan_count = 0;
        g_done = 0;
    }
}

// ---------------- launcher ----------------
extern "C" void kernel_launch(void* const* d_in, const int* in_sizes, int n_in,
                              void* d_out, int out_size) {
    const float* seq = (const float*)d_in[0];
    const int* cid = (const int*)d_in[1];   // int32 or int64 -- probed in-kernel
    float* out = (float*)d_out;

    dim3 grid(NBLK_X, NB);
    k1_fused<<<grid, 256>>>(seq, cid, out);
}